// round 13
// baseline (speedup 1.0000x reference)
#include <cuda_runtime.h>
#include <cuda_fp16.h>
#include <stdint.h>

// ---------------------------------------------------------------------------
// GCNConv on GB300 (sm_103a, compute_103 PTX target)
//   CSR counting-sort aggregation; single-pass TF32 mma.sync GEMM; GEMM
//   overlapped with CSR build (fork/join); xlin fp16; premultiplied edge norm;
//   g_cnt self-zeroing in accum (no memset launch).
// edge_index is int32 on device (JAX x64 disabled).
// ---------------------------------------------------------------------------

#define NMAX 100000
#define EMAX 1600000
#define DIM  128
#define SCAN_BS 512
#define SCAN_BLOCKS ((NMAX + SCAN_BS - 1) / SCAN_BS)   // 196

__device__ int    g_cnt [NMAX];     // static zero-init; re-zeroed by k_accum
__device__ int    g_start[NMAX];
__device__ int    g_cur [NMAX];
__device__ float  g_dinv[NMAX];
__device__ int    g_bsum[SCAN_BLOCKS];
__device__ int    g_scantmp[NMAX];
__device__ int2   g_edge[EMAX];            // {src, __float_as_int(norm)}
__device__ __half g_xlin_h[(size_t)NMAX * DIM];

// ----------------------------- histogram (x4) --------------------------------
__global__ void k_hist(const int* __restrict__ ei, int E) {
    int i = blockIdx.x * blockDim.x + threadIdx.x;   // E/4 threads
    int e = i * 4;
    if (e < E) {
        int4 d4 = *reinterpret_cast<const int4*>(ei + E + e);
        atomicAdd(&g_cnt[d4.x], 1);
        atomicAdd(&g_cnt[d4.y], 1);
        atomicAdd(&g_cnt[d4.z], 1);
        atomicAdd(&g_cnt[d4.w], 1);
    }
}

// ------------------------- scan pass 1 (+dinv fused) -------------------------
__global__ void k_scan1(int N) {
    __shared__ int sm[SCAN_BS];
    int i = blockIdx.x * SCAN_BS + threadIdx.x;
    int v = (i < N) ? g_cnt[i] : 0;
    if (i < N) g_dinv[i] = rsqrtf((float)(v + 1));
    sm[threadIdx.x] = v;
    __syncthreads();
#pragma unroll
    for (int ofs = 1; ofs < SCAN_BS; ofs <<= 1) {
        int t = (threadIdx.x >= ofs) ? sm[threadIdx.x - ofs] : 0;
        __syncthreads();
        sm[threadIdx.x] += t;
        __syncthreads();
    }
    if (i < N) g_scantmp[i] = sm[threadIdx.x] - v;
    if (threadIdx.x == SCAN_BS - 1) g_bsum[blockIdx.x] = sm[threadIdx.x];
}

// --------------- scan pass 2: per-block bsum reduction + finalize -------------
__global__ void k_scan3(int N) {
    int t = threadIdx.x;
    int i = blockIdx.x * 256 + t;
    int sb = blockIdx.x >> 1;

    int v = (t < sb) ? g_bsum[t] : 0;   // SCAN_BLOCKS=196 <= 256
#pragma unroll
    for (int o = 16; o > 0; o >>= 1) v += __shfl_down_sync(0xffffffffu, v, o);
    __shared__ int wsum[8];
    if ((t & 31) == 0) wsum[t >> 5] = v;
    __syncthreads();
    __shared__ int pre_s;
    if (t < 8) {
        int s = wsum[t];
#pragma unroll
        for (int o = 4; o > 0; o >>= 1) s += __shfl_down_sync(0x000000ffu, s, o);
        if (t == 0) pre_s = s;
    }
    __syncthreads();

    if (i < N) {
        int s = g_scantmp[i] + pre_s;
        g_start[i] = s;
        g_cur[i] = s;
    }
}

// ----------------------------- bucket (x2) -----------------------------------
__global__ void k_bucket(const int* __restrict__ ei, int E) {
    int i = blockIdx.x * blockDim.x + threadIdx.x;   // E/2 threads
    int e = i * 2;
    if (e < E) {
        int2 s2 = *reinterpret_cast<const int2*>(ei + e);
        int2 d2 = *reinterpret_cast<const int2*>(ei + E + e);
        float n0 = g_dinv[s2.x] * g_dinv[d2.x];
        float n1 = g_dinv[s2.y] * g_dinv[d2.y];
        int p0 = atomicAdd(&g_cur[d2.x], 1);
        g_edge[p0] = make_int2(s2.x, __float_as_int(n0));
        int p1 = atomicAdd(&g_cur[d2.y], 1);
        g_edge[p1] = make_int2(s2.y, __float_as_int(n1));
    }
}

// ------------------------- mma.sync TF32 GEMM (single pass) ------------------
#define PA 68
#define PW 136
#define XS 0
#define WS (128 * PA)
#define SM_FLOATS (128 * PA + 64 * PW)   // 69632 B

__device__ __forceinline__ uint32_t tf32_of(float v) {
    uint32_t r;
    asm("cvt.rna.tf32.f32 %0, %1;" : "=r"(r) : "f"(v));
    return r;
}

__device__ __forceinline__ void mma_tf32(float c[4], uint32_t a0, uint32_t a1,
                                         uint32_t a2, uint32_t a3,
                                         uint32_t b0, uint32_t b1) {
    asm volatile(
        "mma.sync.aligned.m16n8k8.row.col.f32.tf32.tf32.f32 "
        "{%0,%1,%2,%3}, {%4,%5,%6,%7}, {%8,%9}, {%0,%1,%2,%3};"
        : "+f"(c[0]), "+f"(c[1]), "+f"(c[2]), "+f"(c[3])
        : "r"(a0), "r"(a1), "r"(a2), "r"(a3), "r"(b0), "r"(b1));
}

__global__ void __launch_bounds__(256) k_gemm_mma(const float* __restrict__ x,
                                                  const float* __restrict__ W, int N) {
    extern __shared__ float sm[];
    int t = threadIdx.x;
    int lane = t & 31, w = t >> 5;
    int tg = lane >> 2, tq = lane & 3;
    int mwarp = (w >> 1) * 32;
    int nwarp = (w & 1) * 64;
    int row0 = blockIdx.x * 128;

    const float4* x4 = reinterpret_cast<const float4*>(x);
    const float4* W4 = reinterpret_cast<const float4*>(W);

    float acc[2][8][4];
#pragma unroll
    for (int mt = 0; mt < 2; mt++)
#pragma unroll
        for (int nt = 0; nt < 8; nt++)
#pragma unroll
            for (int c = 0; c < 4; c++) acc[mt][nt][c] = 0.f;

    for (int kc = 0; kc < 2; kc++) {
        for (int i = t; i < 2048; i += 256) {
            int r = i >> 4, q = i & 15;
            int gr = row0 + r;
            float4 v = (gr < N) ? x4[(size_t)gr * 32 + kc * 16 + q]
                                : make_float4(0.f, 0.f, 0.f, 0.f);
            *reinterpret_cast<float4*>(&sm[XS + r * PA + q * 4]) = v;
        }
        for (int i = t; i < 2048; i += 256) {
            int o = i & 127, q = i >> 7;
            float4 v = W4[(size_t)o * 32 + kc * 16 + q];
            sm[WS + (q * 4 + 0) * PW + o] = v.x;
            sm[WS + (q * 4 + 1) * PW + o] = v.y;
            sm[WS + (q * 4 + 2) * PW + o] = v.z;
            sm[WS + (q * 4 + 3) * PW + o] = v.w;
        }
        __syncthreads();

#pragma unroll
        for (int ks = 0; ks < 8; ks++) {
            int kb = ks * 8;
            uint32_t a[2][4];
#pragma unroll
            for (int mt = 0; mt < 2; mt++) {
                int mrow = mwarp + mt * 16 + tg;
                a[mt][0] = tf32_of(sm[XS + (mrow    ) * PA + kb + tq]);
                a[mt][1] = tf32_of(sm[XS + (mrow + 8) * PA + kb + tq]);
                a[mt][2] = tf32_of(sm[XS + (mrow    ) * PA + kb + tq + 4]);
                a[mt][3] = tf32_of(sm[XS + (mrow + 8) * PA + kb + tq + 4]);
            }
#pragma unroll
            for (int nt = 0; nt < 8; nt++) {
                int o = nwarp + nt * 8 + tg;
                uint32_t b0 = tf32_of(sm[WS + (kb + tq    ) * PW + o]);
                uint32_t b1 = tf32_of(sm[WS + (kb + tq + 4) * PW + o]);
#pragma unroll
                for (int mt = 0; mt < 2; mt++)
                    mma_tf32(acc[mt][nt], a[mt][0], a[mt][1], a[mt][2], a[mt][3], b0, b1);
            }
        }
        __syncthreads();
    }

#pragma unroll
    for (int mt = 0; mt < 2; mt++) {
        int gr = row0 + mwarp + mt * 16 + tg;
#pragma unroll
        for (int nt = 0; nt < 8; nt++) {
            int gc = nwarp + nt * 8 + tq * 2;
            if (gr < N)
                *reinterpret_cast<__half2*>(&g_xlin_h[(size_t)gr * DIM + gc]) =
                    __floats2half2_rn(acc[mt][nt][0], acc[mt][nt][1]);
            if (gr + 8 < N)
                *reinterpret_cast<__half2*>(&g_xlin_h[(size_t)(gr + 8) * DIM + gc]) =
                    __floats2half2_rn(acc[mt][nt][2], acc[mt][nt][3]);
        }
    }
}

// ------------------------- gather + accumulate (unroll x4) -------------------
__device__ __forceinline__ void fma16(float acc[16], uint4 u0, uint4 u1, float n) {
    const uint32_t* pu = &u0.x;
#pragma unroll
    for (int q = 0; q < 4; q++) {
        float2 f = __half22float2(*reinterpret_cast<const __half2*>(&pu[q]));
        acc[q * 2 + 0] += f.x * n;
        acc[q * 2 + 1] += f.y * n;
    }
    const uint32_t* pv = &u1.x;
#pragma unroll
    for (int q = 0; q < 4; q++) {
        float2 f = __half22float2(*reinterpret_cast<const __half2*>(&pv[q]));
        acc[8 + q * 2 + 0] += f.x * n;
        acc[8 + q * 2 + 1] += f.y * n;
    }
}

__global__ void k_accum(const float* __restrict__ bias, float* __restrict__ out, int N) {
    int d = blockIdx.x * 8 + (threadIdx.x >> 5);
    int lane = threadIdx.x & 31;
    if (d >= N) return;
    int g = lane >> 3, li = lane & 7;

    float dd = g_dinv[d];
    int start = g_start[d];
    int cnt = g_cnt[d];

    float acc[16];
#pragma unroll
    for (int c = 0; c < 16; c++) acc[c] = 0.f;

    if (g == 0) {
        float s2 = dd * dd;
        const uint4* sp = reinterpret_cast<const uint4*>(g_xlin_h + (size_t)d * DIM + li * 16);
        uint4 u0 = sp[0], u1 = sp[1];
        fma16(acc, u0, u1, s2);
#pragma unroll
        for (int q = 0; q < 4; q++) {
            float4 bv = reinterpret_cast<const float4*>(bias)[li * 4 + q];
            acc[q * 4 + 0] += bv.x;
            acc[q * 4 + 1] += bv.y;
            acc[q * 4 + 2] += bv.z;
            acc[q * 4 + 3] += bv.w;
        }
    }

    const int2* recs = g_edge + start;
    int k = g;
    // unroll x4: 4 records + 8 row LDG.128 in flight before first FMA
    for (; k + 12 < cnt; k += 16) {
        int2 r0 = recs[k];
        int2 r1 = recs[k + 4];
        int2 r2 = recs[k + 8];
        int2 r3 = recs[k + 12];
        const uint4* p0 = reinterpret_cast<const uint4*>(g_xlin_h + (size_t)r0.x * DIM + li * 16);
        const uint4* p1 = reinterpret_cast<const uint4*>(g_xlin_h + (size_t)r1.x * DIM + li * 16);
        const uint4* p2 = reinterpret_cast<const uint4*>(g_xlin_h + (size_t)r2.x * DIM + li * 16);
        const uint4* p3 = reinterpret_cast<const uint4*>(g_xlin_h + (size_t)r3.x * DIM + li * 16);
        uint4 a0 = p0[0], a1 = p0[1];
        uint4 b0 = p1[0], b1 = p1[1];
        uint4 c0 = p2[0], c1 = p2[1];
        uint4 e0 = p3[0], e1 = p3[1];
        fma16(acc, a0, a1, __int_as_float(r0.y));
        fma16(acc, b0, b1, __int_as_float(r1.y));
        fma16(acc, c0, c1, __int_as_float(r2.y));
        fma16(acc, e0, e1, __int_as_float(r3.y));
    }
    for (; k < cnt; k += 4) {
        int2 r0 = recs[k];
        const uint4* p0 = reinterpret_cast<const uint4*>(g_xlin_h + (size_t)r0.x * DIM + li * 16);
        uint4 a0 = p0[0], a1 = p0[1];
        fma16(acc, a0, a1, __int_as_float(r0.y));
    }

#pragma unroll
    for (int c = 0; c < 16; c++) {
        acc[c] += __shfl_xor_sync(0xffffffffu, acc[c], 8);
        acc[c] += __shfl_xor_sync(0xffffffffu, acc[c], 16);
    }

    if (g == 0) {
        float4* o4 = reinterpret_cast<float4*>(out + (size_t)d * DIM + li * 16);
#pragma unroll
        for (int q = 0; q < 4; q++)
            o4[q] = make_float4(acc[q * 4 + 0], acc[q * 4 + 1],
                                acc[q * 4 + 2], acc[q * 4 + 3]);
        if (li == 0) g_cnt[d] = 0;   // re-zero for next call (static init = 0)
    }
}

// ------------------------------- launcher ------------------------------------
extern "C" void kernel_launch(void* const* d_in, const int* in_sizes, int n_in,
                              void* d_out, int out_size) {
    const float* x  = (const float*)d_in[0];
    const int*   ei = (const int*)d_in[1];
    const float* W  = (const float*)d_in[2];
    const float* b  = (const float*)d_in[3];
    float*       out = (float*)d_out;

    int N = in_sizes[0] / DIM;   // 100000
    int E = in_sizes[1] / 2;     // 1600000

    static cudaStream_t s2 = 0;
    static cudaEvent_t ev_fork = 0, ev_join = 0;
    static bool init_done = false;
    if (!init_done) {
        if (cudaStreamCreateWithFlags(&s2, cudaStreamNonBlocking) != cudaSuccess) s2 = 0;
        cudaEventCreateWithFlags(&ev_fork, cudaEventDisableTiming);
        cudaEventCreateWithFlags(&ev_join, cudaEventDisableTiming);
        init_done = true;
    }

    const int T = 256;
    int smem_bytes = SM_FLOATS * sizeof(float);
    cudaFuncSetAttribute(k_gemm_mma, cudaFuncAttributeMaxDynamicSharedMemorySize, smem_bytes);

    bool fork = (s2 != 0) && ev_fork && ev_join;

    if (fork) {
        cudaEventRecord(ev_fork, 0);
        cudaStreamWaitEvent(s2, ev_fork, 0);
        k_gemm_mma<<<(N + 127) / 128, 256, smem_bytes, s2>>>(x, W, N);
        cudaEventRecord(ev_join, s2);
    }

    k_hist<<<(E / 4 + T - 1) / T, T>>>(ei, E);
    k_scan1<<<SCAN_BLOCKS, SCAN_BS>>>(N);
    k_scan3<<<(N + 255) / 256, 256>>>(N);
    k_bucket<<<(E / 2 + T - 1) / T, T>>>(ei, E);

    if (fork) {
        cudaStreamWaitEvent(0, ev_join, 0);
    } else {
        k_gemm_mma<<<(N + 127) / 128, 256, smem_bytes>>>(x, W, N);
    }

    k_accum<<<(N + 7) / 8, 256>>>(b, out, N);
}

// round 14
// speedup vs baseline: 1.0388x; 1.0388x over previous
#include <cuda_runtime.h>
#include <cuda_fp16.h>
#include <stdint.h>

// ---------------------------------------------------------------------------
// GCNConv on GB300 (sm_103a, compute_103 PTX target)
//   CSR counting-sort aggregation; single-pass TF32 mma.sync GEMM; GEMM
//   overlapped with CSR build (fork/join); xlin fp16; premultiplied edge norm;
//   g_cnt self-zeroing in accum (no memset launch).  [R12 structure]
// edge_index is int32 on device (JAX x64 disabled).
// ---------------------------------------------------------------------------

#define NMAX 100000
#define EMAX 1600000
#define DIM  128
#define SCAN_BS 512
#define SCAN_BLOCKS ((NMAX + SCAN_BS - 1) / SCAN_BS)   // 196

__device__ int    g_cnt [NMAX];     // static zero-init; re-zeroed by k_accum
__device__ int    g_start[NMAX];
__device__ int    g_cur [NMAX];
__device__ float  g_dinv[NMAX];
__device__ int    g_bsum[SCAN_BLOCKS];
__device__ int    g_scantmp[NMAX];
__device__ int2   g_edge[EMAX];            // {src, __float_as_int(norm)}
__device__ __half g_xlin_h[(size_t)NMAX * DIM];

// ----------------------------- histogram -------------------------------------
__global__ void k_hist(const int* __restrict__ ei, int E) {
    int e = blockIdx.x * blockDim.x + threadIdx.x;
    if (e < E) atomicAdd(&g_cnt[ei[E + e]], 1);
}

// ------------------------- scan pass 1 (+dinv fused) -------------------------
__global__ void k_scan1(int N) {
    __shared__ int sm[SCAN_BS];
    int i = blockIdx.x * SCAN_BS + threadIdx.x;
    int v = (i < N) ? g_cnt[i] : 0;
    if (i < N) g_dinv[i] = rsqrtf((float)(v + 1));
    sm[threadIdx.x] = v;
    __syncthreads();
#pragma unroll
    for (int ofs = 1; ofs < SCAN_BS; ofs <<= 1) {
        int t = (threadIdx.x >= ofs) ? sm[threadIdx.x - ofs] : 0;
        __syncthreads();
        sm[threadIdx.x] += t;
        __syncthreads();
    }
    if (i < N) g_scantmp[i] = sm[threadIdx.x] - v;
    if (threadIdx.x == SCAN_BS - 1) g_bsum[blockIdx.x] = sm[threadIdx.x];
}

// --------------- scan pass 2: per-block bsum reduction + finalize -------------
__global__ void k_scan3(int N) {
    int t = threadIdx.x;
    int i = blockIdx.x * 256 + t;
    int sb = blockIdx.x >> 1;

    int v = (t < sb) ? g_bsum[t] : 0;   // SCAN_BLOCKS=196 <= 256
#pragma unroll
    for (int o = 16; o > 0; o >>= 1) v += __shfl_down_sync(0xffffffffu, v, o);
    __shared__ int wsum[8];
    if ((t & 31) == 0) wsum[t >> 5] = v;
    __syncthreads();
    __shared__ int pre_s;
    if (t < 8) {
        int s = wsum[t];
#pragma unroll
        for (int o = 4; o > 0; o >>= 1) s += __shfl_down_sync(0x000000ffu, s, o);
        if (t == 0) pre_s = s;
    }
    __syncthreads();

    if (i < N) {
        int s = g_scantmp[i] + pre_s;
        g_start[i] = s;
        g_cur[i] = s;
    }
}

// ----------------------------- bucket ----------------------------------------
__global__ void k_bucket(const int* __restrict__ ei, int E) {
    int e = blockIdx.x * blockDim.x + threadIdx.x;
    if (e < E) {
        int s = ei[e];
        int d = ei[E + e];
        float nm = g_dinv[s] * g_dinv[d];
        int pos = atomicAdd(&g_cur[d], 1);
        g_edge[pos] = make_int2(s, __float_as_int(nm));
    }
}

// ------------------------- mma.sync TF32 GEMM (single pass) ------------------
#define PA 68
#define PW 136
#define XS 0
#define WS (128 * PA)
#define SM_FLOATS (128 * PA + 64 * PW)   // 69632 B

__device__ __forceinline__ uint32_t tf32_of(float v) {
    uint32_t r;
    asm("cvt.rna.tf32.f32 %0, %1;" : "=r"(r) : "f"(v));
    return r;
}

__device__ __forceinline__ void mma_tf32(float c[4], uint32_t a0, uint32_t a1,
                                         uint32_t a2, uint32_t a3,
                                         uint32_t b0, uint32_t b1) {
    asm volatile(
        "mma.sync.aligned.m16n8k8.row.col.f32.tf32.tf32.f32 "
        "{%0,%1,%2,%3}, {%4,%5,%6,%7}, {%8,%9}, {%0,%1,%2,%3};"
        : "+f"(c[0]), "+f"(c[1]), "+f"(c[2]), "+f"(c[3])
        : "r"(a0), "r"(a1), "r"(a2), "r"(a3), "r"(b0), "r"(b1));
}

__global__ void __launch_bounds__(256) k_gemm_mma(const float* __restrict__ x,
                                                  const float* __restrict__ W, int N) {
    extern __shared__ float sm[];
    int t = threadIdx.x;
    int lane = t & 31, w = t >> 5;
    int tg = lane >> 2, tq = lane & 3;
    int mwarp = (w >> 1) * 32;
    int nwarp = (w & 1) * 64;
    int row0 = blockIdx.x * 128;

    const float4* x4 = reinterpret_cast<const float4*>(x);
    const float4* W4 = reinterpret_cast<const float4*>(W);

    float acc[2][8][4];
#pragma unroll
    for (int mt = 0; mt < 2; mt++)
#pragma unroll
        for (int nt = 0; nt < 8; nt++)
#pragma unroll
            for (int c = 0; c < 4; c++) acc[mt][nt][c] = 0.f;

    for (int kc = 0; kc < 2; kc++) {
        for (int i = t; i < 2048; i += 256) {
            int r = i >> 4, q = i & 15;
            int gr = row0 + r;
            float4 v = (gr < N) ? x4[(size_t)gr * 32 + kc * 16 + q]
                                : make_float4(0.f, 0.f, 0.f, 0.f);
            *reinterpret_cast<float4*>(&sm[XS + r * PA + q * 4]) = v;
        }
        for (int i = t; i < 2048; i += 256) {
            int o = i & 127, q = i >> 7;
            float4 v = W4[(size_t)o * 32 + kc * 16 + q];
            sm[WS + (q * 4 + 0) * PW + o] = v.x;
            sm[WS + (q * 4 + 1) * PW + o] = v.y;
            sm[WS + (q * 4 + 2) * PW + o] = v.z;
            sm[WS + (q * 4 + 3) * PW + o] = v.w;
        }
        __syncthreads();

#pragma unroll
        for (int ks = 0; ks < 8; ks++) {
            int kb = ks * 8;
            uint32_t a[2][4];
#pragma unroll
            for (int mt = 0; mt < 2; mt++) {
                int mrow = mwarp + mt * 16 + tg;
                a[mt][0] = tf32_of(sm[XS + (mrow    ) * PA + kb + tq]);
                a[mt][1] = tf32_of(sm[XS + (mrow + 8) * PA + kb + tq]);
                a[mt][2] = tf32_of(sm[XS + (mrow    ) * PA + kb + tq + 4]);
                a[mt][3] = tf32_of(sm[XS + (mrow + 8) * PA + kb + tq + 4]);
            }
#pragma unroll
            for (int nt = 0; nt < 8; nt++) {
                int o = nwarp + nt * 8 + tg;
                uint32_t b0 = tf32_of(sm[WS + (kb + tq    ) * PW + o]);
                uint32_t b1 = tf32_of(sm[WS + (kb + tq + 4) * PW + o]);
#pragma unroll
                for (int mt = 0; mt < 2; mt++)
                    mma_tf32(acc[mt][nt], a[mt][0], a[mt][1], a[mt][2], a[mt][3], b0, b1);
            }
        }
        __syncthreads();
    }

#pragma unroll
    for (int mt = 0; mt < 2; mt++) {
        int gr = row0 + mwarp + mt * 16 + tg;
#pragma unroll
        for (int nt = 0; nt < 8; nt++) {
            int gc = nwarp + nt * 8 + tq * 2;
            if (gr < N)
                *reinterpret_cast<__half2*>(&g_xlin_h[(size_t)gr * DIM + gc]) =
                    __floats2half2_rn(acc[mt][nt][0], acc[mt][nt][1]);
            if (gr + 8 < N)
                *reinterpret_cast<__half2*>(&g_xlin_h[(size_t)(gr + 8) * DIM + gc]) =
                    __floats2half2_rn(acc[mt][nt][2], acc[mt][nt][3]);
        }
    }
}

// ------------------------- gather + accumulate (unroll x2) -------------------
__device__ __forceinline__ void fma16(float acc[16], uint4 u0, uint4 u1, float n) {
    const uint32_t* pu = &u0.x;
#pragma unroll
    for (int q = 0; q < 4; q++) {
        float2 f = __half22float2(*reinterpret_cast<const __half2*>(&pu[q]));
        acc[q * 2 + 0] += f.x * n;
        acc[q * 2 + 1] += f.y * n;
    }
    const uint32_t* pv = &u1.x;
#pragma unroll
    for (int q = 0; q < 4; q++) {
        float2 f = __half22float2(*reinterpret_cast<const __half2*>(&pv[q]));
        acc[8 + q * 2 + 0] += f.x * n;
        acc[8 + q * 2 + 1] += f.y * n;
    }
}

__global__ void k_accum(const float* __restrict__ bias, float* __restrict__ out, int N) {
    int d = blockIdx.x * 8 + (threadIdx.x >> 5);
    int lane = threadIdx.x & 31;
    if (d >= N) return;
    int g = lane >> 3, li = lane & 7;

    float dd = g_dinv[d];
    int start = g_start[d];
    int cnt = g_cnt[d];

    float acc[16];
#pragma unroll
    for (int c = 0; c < 16; c++) acc[c] = 0.f;

    if (g == 0) {
        float s2 = dd * dd;
        const uint4* sp = reinterpret_cast<const uint4*>(g_xlin_h + (size_t)d * DIM + li * 16);
        uint4 u0 = sp[0], u1 = sp[1];
        fma16(acc, u0, u1, s2);
#pragma unroll
        for (int q = 0; q < 4; q++) {
            float4 bv = reinterpret_cast<const float4*>(bias)[li * 4 + q];
            acc[q * 4 + 0] += bv.x;
            acc[q * 4 + 1] += bv.y;
            acc[q * 4 + 2] += bv.z;
            acc[q * 4 + 3] += bv.w;
        }
    }

    const int2* recs = g_edge + start;
    int k = g;
    // unroll x2: 2 records + 4 row LDG.128 in flight before first FMA
    for (; k + 4 < cnt; k += 8) {
        int2 r0 = recs[k];
        int2 r1 = recs[k + 4];
        const uint4* p0 = reinterpret_cast<const uint4*>(
            g_xlin_h + (size_t)r0.x * DIM + li * 16);
        const uint4* p1 = reinterpret_cast<const uint4*>(
            g_xlin_h + (size_t)r1.x * DIM + li * 16);
        uint4 a0 = p0[0], a1 = p0[1];
        uint4 b0 = p1[0], b1 = p1[1];
        fma16(acc, a0, a1, __int_as_float(r0.y));
        fma16(acc, b0, b1, __int_as_float(r1.y));
    }
    if (k < cnt) {
        int2 r0 = recs[k];
        const uint4* p0 = reinterpret_cast<const uint4*>(
            g_xlin_h + (size_t)r0.x * DIM + li * 16);
        uint4 a0 = p0[0], a1 = p0[1];
        fma16(acc, a0, a1, __int_as_float(r0.y));
    }

#pragma unroll
    for (int c = 0; c < 16; c++) {
        acc[c] += __shfl_xor_sync(0xffffffffu, acc[c], 8);
        acc[c] += __shfl_xor_sync(0xffffffffu, acc[c], 16);
    }

    if (g == 0) {
        float4* o4 = reinterpret_cast<float4*>(out + (size_t)d * DIM + li * 16);
#pragma unroll
        for (int q = 0; q < 4; q++)
            o4[q] = make_float4(acc[q * 4 + 0], acc[q * 4 + 1],
                                acc[q * 4 + 2], acc[q * 4 + 3]);
        if (li == 0) g_cnt[d] = 0;   // re-zero for next call (static init = 0)
    }
}

// ------------------------------- launcher ------------------------------------
extern "C" void kernel_launch(void* const* d_in, const int* in_sizes, int n_in,
                              void* d_out, int out_size) {
    const float* x  = (const float*)d_in[0];
    const int*   ei = (const int*)d_in[1];
    const float* W  = (const float*)d_in[2];
    const float* b  = (const float*)d_in[3];
    float*       out = (float*)d_out;

    int N = in_sizes[0] / DIM;   // 100000
    int E = in_sizes[1] / 2;     // 1600000

    static cudaStream_t s2 = 0;
    static cudaEvent_t ev_fork = 0, ev_join = 0;
    static bool init_done = false;
    if (!init_done) {
        if (cudaStreamCreateWithFlags(&s2, cudaStreamNonBlocking) != cudaSuccess) s2 = 0;
        cudaEventCreateWithFlags(&ev_fork, cudaEventDisableTiming);
        cudaEventCreateWithFlags(&ev_join, cudaEventDisableTiming);
        init_done = true;
    }

    const int T = 256;
    int smem_bytes = SM_FLOATS * sizeof(float);
    cudaFuncSetAttribute(k_gemm_mma, cudaFuncAttributeMaxDynamicSharedMemorySize, smem_bytes);

    bool fork = (s2 != 0) && ev_fork && ev_join;

    if (fork) {
        cudaEventRecord(ev_fork, 0);
        cudaStreamWaitEvent(s2, ev_fork, 0);
        k_gemm_mma<<<(N + 127) / 128, 256, smem_bytes, s2>>>(x, W, N);
        cudaEventRecord(ev_join, s2);
    }

    k_hist<<<(E + T - 1) / T, T>>>(ei, E);
    k_scan1<<<SCAN_BLOCKS, SCAN_BS>>>(N);
    k_scan3<<<(N + 255) / 256, 256>>>(N);
    k_bucket<<<(E + T - 1) / T, T>>>(ei, E);

    if (fork) {
        cudaStreamWaitEvent(0, ev_join, 0);
    } else {
        k_gemm_mma<<<(N + 127) / 128, 256, smem_bytes>>>(x, W, N);
    }

    k_accum<<<(N + 7) / 8, 256>>>(b, out, N);
}

// round 15
// speedup vs baseline: 1.0927x; 1.0519x over previous
#include <cuda_runtime.h>
#include <cuda_fp16.h>
#include <stdint.h>

// ---------------------------------------------------------------------------
// GCNConv on GB300 (sm_103a, compute_103 PTX target)
//   CSR counting-sort aggregation; single-pass TF32 mma.sync GEMM; GEMM
//   overlapped with CSR build (fork/join); xlin fp16; premultiplied edge norm.
//   [R12 structure; accum uses 2 groups x 16 lanes]
// edge_index is int32 on device (JAX x64 disabled).
// ---------------------------------------------------------------------------

#define NMAX 100000
#define EMAX 1600000
#define DIM  128
#define SCAN_BS 512
#define SCAN_BLOCKS ((NMAX + SCAN_BS - 1) / SCAN_BS)   // 196

__device__ int    g_cnt [NMAX];
__device__ int    g_start[NMAX];
__device__ int    g_cur [NMAX];
__device__ float  g_dinv[NMAX];
__device__ int    g_bsum[SCAN_BLOCKS];
__device__ int    g_scantmp[NMAX];
__device__ int2   g_edge[EMAX];            // {src, __float_as_int(norm)}
__device__ __half g_xlin_h[(size_t)NMAX * DIM];

// ----------------------------- histogram -------------------------------------
__global__ void k_hist(const int* __restrict__ ei, int E) {
    int e = blockIdx.x * blockDim.x + threadIdx.x;
    if (e < E) atomicAdd(&g_cnt[ei[E + e]], 1);
}

// ------------------------- scan pass 1 (+dinv fused) -------------------------
__global__ void k_scan1(int N) {
    __shared__ int sm[SCAN_BS];
    int i = blockIdx.x * SCAN_BS + threadIdx.x;
    int v = (i < N) ? g_cnt[i] : 0;
    if (i < N) g_dinv[i] = rsqrtf((float)(v + 1));
    sm[threadIdx.x] = v;
    __syncthreads();
#pragma unroll
    for (int ofs = 1; ofs < SCAN_BS; ofs <<= 1) {
        int t = (threadIdx.x >= ofs) ? sm[threadIdx.x - ofs] : 0;
        __syncthreads();
        sm[threadIdx.x] += t;
        __syncthreads();
    }
    if (i < N) g_scantmp[i] = sm[threadIdx.x] - v;
    if (threadIdx.x == SCAN_BS - 1) g_bsum[blockIdx.x] = sm[threadIdx.x];
}

// --------------- scan pass 2: per-block bsum reduction + finalize -------------
__global__ void k_scan3(int N) {
    int t = threadIdx.x;
    int i = blockIdx.x * 256 + t;
    int sb = blockIdx.x >> 1;

    int v = (t < sb) ? g_bsum[t] : 0;   // SCAN_BLOCKS=196 <= 256
#pragma unroll
    for (int o = 16; o > 0; o >>= 1) v += __shfl_down_sync(0xffffffffu, v, o);
    __shared__ int wsum[8];
    if ((t & 31) == 0) wsum[t >> 5] = v;
    __syncthreads();
    __shared__ int pre_s;
    if (t < 8) {
        int s = wsum[t];
#pragma unroll
        for (int o = 4; o > 0; o >>= 1) s += __shfl_down_sync(0x000000ffu, s, o);
        if (t == 0) pre_s = s;
    }
    __syncthreads();

    if (i < N) {
        int s = g_scantmp[i] + pre_s;
        g_start[i] = s;
        g_cur[i] = s;
    }
}

// ----------------------------- bucket ----------------------------------------
__global__ void k_bucket(const int* __restrict__ ei, int E) {
    int e = blockIdx.x * blockDim.x + threadIdx.x;
    if (e < E) {
        int s = ei[e];
        int d = ei[E + e];
        float nm = g_dinv[s] * g_dinv[d];
        int pos = atomicAdd(&g_cur[d], 1);
        g_edge[pos] = make_int2(s, __float_as_int(nm));
    }
}

// ------------------------- mma.sync TF32 GEMM (single pass) ------------------
#define PA 68
#define PW 136
#define XS 0
#define WS (128 * PA)
#define SM_FLOATS (128 * PA + 64 * PW)   // 69632 B

__device__ __forceinline__ uint32_t tf32_of(float v) {
    uint32_t r;
    asm("cvt.rna.tf32.f32 %0, %1;" : "=r"(r) : "f"(v));
    return r;
}

__device__ __forceinline__ void mma_tf32(float c[4], uint32_t a0, uint32_t a1,
                                         uint32_t a2, uint32_t a3,
                                         uint32_t b0, uint32_t b1) {
    asm volatile(
        "mma.sync.aligned.m16n8k8.row.col.f32.tf32.tf32.f32 "
        "{%0,%1,%2,%3}, {%4,%5,%6,%7}, {%8,%9}, {%0,%1,%2,%3};"
        : "+f"(c[0]), "+f"(c[1]), "+f"(c[2]), "+f"(c[3])
        : "r"(a0), "r"(a1), "r"(a2), "r"(a3), "r"(b0), "r"(b1));
}

__global__ void __launch_bounds__(256) k_gemm_mma(const float* __restrict__ x,
                                                  const float* __restrict__ W, int N) {
    extern __shared__ float sm[];
    int t = threadIdx.x;
    int lane = t & 31, w = t >> 5;
    int tg = lane >> 2, tq = lane & 3;
    int mwarp = (w >> 1) * 32;
    int nwarp = (w & 1) * 64;
    int row0 = blockIdx.x * 128;

    const float4* x4 = reinterpret_cast<const float4*>(x);
    const float4* W4 = reinterpret_cast<const float4*>(W);

    float acc[2][8][4];
#pragma unroll
    for (int mt = 0; mt < 2; mt++)
#pragma unroll
        for (int nt = 0; nt < 8; nt++)
#pragma unroll
            for (int c = 0; c < 4; c++) acc[mt][nt][c] = 0.f;

    for (int kc = 0; kc < 2; kc++) {
        for (int i = t; i < 2048; i += 256) {
            int r = i >> 4, q = i & 15;
            int gr = row0 + r;
            float4 v = (gr < N) ? x4[(size_t)gr * 32 + kc * 16 + q]
                                : make_float4(0.f, 0.f, 0.f, 0.f);
            *reinterpret_cast<float4*>(&sm[XS + r * PA + q * 4]) = v;
        }
        for (int i = t; i < 2048; i += 256) {
            int o = i & 127, q = i >> 7;
            float4 v = W4[(size_t)o * 32 + kc * 16 + q];
            sm[WS + (q * 4 + 0) * PW + o] = v.x;
            sm[WS + (q * 4 + 1) * PW + o] = v.y;
            sm[WS + (q * 4 + 2) * PW + o] = v.z;
            sm[WS + (q * 4 + 3) * PW + o] = v.w;
        }
        __syncthreads();

#pragma unroll
        for (int ks = 0; ks < 8; ks++) {
            int kb = ks * 8;
            uint32_t a[2][4];
#pragma unroll
            for (int mt = 0; mt < 2; mt++) {
                int mrow = mwarp + mt * 16 + tg;
                a[mt][0] = tf32_of(sm[XS + (mrow    ) * PA + kb + tq]);
                a[mt][1] = tf32_of(sm[XS + (mrow + 8) * PA + kb + tq]);
                a[mt][2] = tf32_of(sm[XS + (mrow    ) * PA + kb + tq + 4]);
                a[mt][3] = tf32_of(sm[XS + (mrow + 8) * PA + kb + tq + 4]);
            }
#pragma unroll
            for (int nt = 0; nt < 8; nt++) {
                int o = nwarp + nt * 8 + tg;
                uint32_t b0 = tf32_of(sm[WS + (kb + tq    ) * PW + o]);
                uint32_t b1 = tf32_of(sm[WS + (kb + tq + 4) * PW + o]);
#pragma unroll
                for (int mt = 0; mt < 2; mt++)
                    mma_tf32(acc[mt][nt], a[mt][0], a[mt][1], a[mt][2], a[mt][3], b0, b1);
            }
        }
        __syncthreads();
    }

#pragma unroll
    for (int mt = 0; mt < 2; mt++) {
        int gr = row0 + mwarp + mt * 16 + tg;
#pragma unroll
        for (int nt = 0; nt < 8; nt++) {
            int gc = nwarp + nt * 8 + tq * 2;
            if (gr < N)
                *reinterpret_cast<__half2*>(&g_xlin_h[(size_t)gr * DIM + gc]) =
                    __floats2half2_rn(acc[mt][nt][0], acc[mt][nt][1]);
            if (gr + 8 < N)
                *reinterpret_cast<__half2*>(&g_xlin_h[(size_t)(gr + 8) * DIM + gc]) =
                    __floats2half2_rn(acc[mt][nt][2], acc[mt][nt][3]);
        }
    }
}

// ---------------- gather + accumulate (2 groups x 16 lanes) ------------------
// Lane covers 8 fp16 cols (one uint4 = 16 B); 16 lanes span the full row.
// Each warp step: 2 groups x 2 edges (unroll x2) = 4 row LDG.128 in flight.
__device__ __forceinline__ void fma8(float acc[8], uint4 u, float n) {
    const uint32_t* pu = &u.x;
#pragma unroll
    for (int q = 0; q < 4; q++) {
        float2 f = __half22float2(*reinterpret_cast<const __half2*>(&pu[q]));
        acc[q * 2 + 0] += f.x * n;
        acc[q * 2 + 1] += f.y * n;
    }
}

__global__ void k_accum(const float* __restrict__ bias, float* __restrict__ out, int N) {
    int d = blockIdx.x * 8 + (threadIdx.x >> 5);
    int lane = threadIdx.x & 31;
    if (d >= N) return;
    int g = lane >> 4, li = lane & 15;

    float dd = g_dinv[d];
    int start = g_start[d];
    int cnt = g_cnt[d];

    float acc[8];
#pragma unroll
    for (int c = 0; c < 8; c++) acc[c] = 0.f;

    if (g == 0) {
        float s2 = dd * dd;
        uint4 u = *reinterpret_cast<const uint4*>(g_xlin_h + (size_t)d * DIM + li * 8);
        fma8(acc, u, s2);
    } else {
        float2 b0 = reinterpret_cast<const float2*>(bias)[li * 4 + 0];
        float2 b1 = reinterpret_cast<const float2*>(bias)[li * 4 + 1];
        float2 b2 = reinterpret_cast<const float2*>(bias)[li * 4 + 2];
        float2 b3 = reinterpret_cast<const float2*>(bias)[li * 4 + 3];
        acc[0] += b0.x; acc[1] += b0.y;
        acc[2] += b1.x; acc[3] += b1.y;
        acc[4] += b2.x; acc[5] += b2.y;
        acc[6] += b3.x; acc[7] += b3.y;
    }

    const int2* recs = g_edge + start;
    int k = g;
    // unroll x2: per step 2 records/group -> 4 independent row LDGs per warp
    for (; k + 2 < cnt; k += 4) {
        int2 r0 = recs[k];
        int2 r1 = recs[k + 2];
        uint4 u0 = *reinterpret_cast<const uint4*>(g_xlin_h + (size_t)r0.x * DIM + li * 8);
        uint4 u1 = *reinterpret_cast<const uint4*>(g_xlin_h + (size_t)r1.x * DIM + li * 8);
        fma8(acc, u0, __int_as_float(r0.y));
        fma8(acc, u1, __int_as_float(r1.y));
    }
    if (k < cnt) {
        int2 r0 = recs[k];
        uint4 u0 = *reinterpret_cast<const uint4*>(g_xlin_h + (size_t)r0.x * DIM + li * 8);
        fma8(acc, u0, __int_as_float(r0.y));
    }

    // combine the 2 group partials
#pragma unroll
    for (int c = 0; c < 8; c++)
        acc[c] += __shfl_xor_sync(0xffffffffu, acc[c], 16);

    if (g == 0) {
        float4* o4 = reinterpret_cast<float4*>(out + (size_t)d * DIM + li * 8);
        o4[0] = make_float4(acc[0], acc[1], acc[2], acc[3]);
        o4[1] = make_float4(acc[4], acc[5], acc[6], acc[7]);
    }
}

// ------------------------------- launcher ------------------------------------
extern "C" void kernel_launch(void* const* d_in, const int* in_sizes, int n_in,
                              void* d_out, int out_size) {
    const float* x  = (const float*)d_in[0];
    const int*   ei = (const int*)d_in[1];
    const float* W  = (const float*)d_in[2];
    const float* b  = (const float*)d_in[3];
    float*       out = (float*)d_out;

    int N = in_sizes[0] / DIM;   // 100000
    int E = in_sizes[1] / 2;     // 1600000

    static cudaStream_t s2 = 0;
    static cudaEvent_t ev_fork = 0, ev_join = 0;
    static void* cnt_addr = 0;
    static bool init_done = false;
    if (!init_done) {
        if (cudaStreamCreateWithFlags(&s2, cudaStreamNonBlocking) != cudaSuccess) s2 = 0;
        cudaEventCreateWithFlags(&ev_fork, cudaEventDisableTiming);
        cudaEventCreateWithFlags(&ev_join, cudaEventDisableTiming);
        cudaGetSymbolAddress(&cnt_addr, g_cnt);
        init_done = true;
    }

    const int T = 256;
    int smem_bytes = SM_FLOATS * sizeof(float);
    cudaFuncSetAttribute(k_gemm_mma, cudaFuncAttributeMaxDynamicSharedMemorySize, smem_bytes);

    bool fork = (s2 != 0) && ev_fork && ev_join;

    if (fork) {
        cudaEventRecord(ev_fork, 0);
        cudaStreamWaitEvent(s2, ev_fork, 0);
        k_gemm_mma<<<(N + 127) / 128, 256, smem_bytes, s2>>>(x, W, N);
        cudaEventRecord(ev_join, s2);
    }

    cudaMemsetAsync(cnt_addr, 0, (size_t)N * sizeof(int), 0);
    k_hist<<<(E + T - 1) / T, T>>>(ei, E);
    k_scan1<<<SCAN_BLOCKS, SCAN_BS>>>(N);
    k_scan3<<<(N + 255) / 256, 256>>>(N);
    k_bucket<<<(E + T - 1) / T, T>>>(ei, E);

    if (fork) {
        cudaStreamWaitEvent(0, ev_join, 0);
    } else {
        k_gemm_mma<<<(N + 127) / 128, 256, smem_bytes>>>(x, W, N);
    }

    k_accum<<<(N + 7) / 8, 256>>>(b, out, N);
}

// round 16
// speedup vs baseline: 1.1039x; 1.0103x over previous
#include <cuda_runtime.h>
#include <cuda_fp16.h>
#include <stdint.h>

// ---------------------------------------------------------------------------
// GCNConv on GB300 (sm_103a, compute_103 PTX target)
//   CSR counting-sort aggregation; single-pass TF32 mma.sync GEMM; GEMM
//   overlapped with CSR build (fork/join); bucket split across both streams;
//   xlin fp16; premultiplied edge norm; __ldg gathers.
// edge_index is int32 on device (JAX x64 disabled).
// ---------------------------------------------------------------------------

#define NMAX 100000
#define EMAX 1600000
#define DIM  128
#define SCAN_BS 512
#define SCAN_BLOCKS ((NMAX + SCAN_BS - 1) / SCAN_BS)   // 196

__device__ int    g_cnt [NMAX];
__device__ int    g_start[NMAX];
__device__ int    g_cur [NMAX];
__device__ float  g_dinv[NMAX];
__device__ int    g_bsum[SCAN_BLOCKS];
__device__ int    g_scantmp[NMAX];
__device__ int2   g_edge[EMAX];            // {src, __float_as_int(norm)}
__device__ __half g_xlin_h[(size_t)NMAX * DIM];

// ----------------------------- histogram -------------------------------------
__global__ void k_hist(const int* __restrict__ ei, int E) {
    int e = blockIdx.x * blockDim.x + threadIdx.x;
    if (e < E) atomicAdd(&g_cnt[ei[E + e]], 1);
}

// ------------------------- scan pass 1 (+dinv fused) -------------------------
__global__ void k_scan1(int N) {
    __shared__ int sm[SCAN_BS];
    int i = blockIdx.x * SCAN_BS + threadIdx.x;
    int v = (i < N) ? g_cnt[i] : 0;
    if (i < N) g_dinv[i] = rsqrtf((float)(v + 1));
    sm[threadIdx.x] = v;
    __syncthreads();
#pragma unroll
    for (int ofs = 1; ofs < SCAN_BS; ofs <<= 1) {
        int t = (threadIdx.x >= ofs) ? sm[threadIdx.x - ofs] : 0;
        __syncthreads();
        sm[threadIdx.x] += t;
        __syncthreads();
    }
    if (i < N) g_scantmp[i] = sm[threadIdx.x] - v;
    if (threadIdx.x == SCAN_BS - 1) g_bsum[blockIdx.x] = sm[threadIdx.x];
}

// --------------- scan pass 2: per-block bsum reduction + finalize -------------
__global__ void k_scan3(int N) {
    int t = threadIdx.x;
    int i = blockIdx.x * 256 + t;
    int sb = blockIdx.x >> 1;

    int v = (t < sb) ? g_bsum[t] : 0;   // SCAN_BLOCKS=196 <= 256
#pragma unroll
    for (int o = 16; o > 0; o >>= 1) v += __shfl_down_sync(0xffffffffu, v, o);
    __shared__ int wsum[8];
    if ((t & 31) == 0) wsum[t >> 5] = v;
    __syncthreads();
    __shared__ int pre_s;
    if (t < 8) {
        int s = wsum[t];
#pragma unroll
        for (int o = 4; o > 0; o >>= 1) s += __shfl_down_sync(0x000000ffu, s, o);
        if (t == 0) pre_s = s;
    }
    __syncthreads();

    if (i < N) {
        int s = g_scantmp[i] + pre_s;
        g_start[i] = s;
        g_cur[i] = s;
    }
}

// ----------------------- bucket (range [e0, e1)) ------------------------------
__global__ void k_bucket(const int* __restrict__ ei, int E, int e0, int e1) {
    int e = e0 + blockIdx.x * blockDim.x + threadIdx.x;
    if (e < e1) {
        int s = ei[e];
        int d = ei[E + e];
        float nm = g_dinv[s] * g_dinv[d];
        int pos = atomicAdd(&g_cur[d], 1);
        g_edge[pos] = make_int2(s, __float_as_int(nm));
    }
}

// ------------------------- mma.sync TF32 GEMM (single pass) ------------------
#define PA 68
#define PW 136
#define XS 0
#define WS (128 * PA)
#define SM_FLOATS (128 * PA + 64 * PW)   // 69632 B

__device__ __forceinline__ uint32_t tf32_of(float v) {
    uint32_t r;
    asm("cvt.rna.tf32.f32 %0, %1;" : "=r"(r) : "f"(v));
    return r;
}

__device__ __forceinline__ void mma_tf32(float c[4], uint32_t a0, uint32_t a1,
                                         uint32_t a2, uint32_t a3,
                                         uint32_t b0, uint32_t b1) {
    asm volatile(
        "mma.sync.aligned.m16n8k8.row.col.f32.tf32.tf32.f32 "
        "{%0,%1,%2,%3}, {%4,%5,%6,%7}, {%8,%9}, {%0,%1,%2,%3};"
        : "+f"(c[0]), "+f"(c[1]), "+f"(c[2]), "+f"(c[3])
        : "r"(a0), "r"(a1), "r"(a2), "r"(a3), "r"(b0), "r"(b1));
}

__global__ void __launch_bounds__(256) k_gemm_mma(const float* __restrict__ x,
                                                  const float* __restrict__ W, int N) {
    extern __shared__ float sm[];
    int t = threadIdx.x;
    int lane = t & 31, w = t >> 5;
    int tg = lane >> 2, tq = lane & 3;
    int mwarp = (w >> 1) * 32;
    int nwarp = (w & 1) * 64;
    int row0 = blockIdx.x * 128;

    const float4* x4 = reinterpret_cast<const float4*>(x);
    const float4* W4 = reinterpret_cast<const float4*>(W);

    float acc[2][8][4];
#pragma unroll
    for (int mt = 0; mt < 2; mt++)
#pragma unroll
        for (int nt = 0; nt < 8; nt++)
#pragma unroll
            for (int c = 0; c < 4; c++) acc[mt][nt][c] = 0.f;

    for (int kc = 0; kc < 2; kc++) {
        for (int i = t; i < 2048; i += 256) {
            int r = i >> 4, q = i & 15;
            int gr = row0 + r;
            float4 v = (gr < N) ? x4[(size_t)gr * 32 + kc * 16 + q]
                                : make_float4(0.f, 0.f, 0.f, 0.f);
            *reinterpret_cast<float4*>(&sm[XS + r * PA + q * 4]) = v;
        }
        for (int i = t; i < 2048; i += 256) {
            int o = i & 127, q = i >> 7;
            float4 v = W4[(size_t)o * 32 + kc * 16 + q];
            sm[WS + (q * 4 + 0) * PW + o] = v.x;
            sm[WS + (q * 4 + 1) * PW + o] = v.y;
            sm[WS + (q * 4 + 2) * PW + o] = v.z;
            sm[WS + (q * 4 + 3) * PW + o] = v.w;
        }
        __syncthreads();

#pragma unroll
        for (int ks = 0; ks < 8; ks++) {
            int kb = ks * 8;
            uint32_t a[2][4];
#pragma unroll
            for (int mt = 0; mt < 2; mt++) {
                int mrow = mwarp + mt * 16 + tg;
                a[mt][0] = tf32_of(sm[XS + (mrow    ) * PA + kb + tq]);
                a[mt][1] = tf32_of(sm[XS + (mrow + 8) * PA + kb + tq]);
                a[mt][2] = tf32_of(sm[XS + (mrow    ) * PA + kb + tq + 4]);
                a[mt][3] = tf32_of(sm[XS + (mrow + 8) * PA + kb + tq + 4]);
            }
#pragma unroll
            for (int nt = 0; nt < 8; nt++) {
                int o = nwarp + nt * 8 + tg;
                uint32_t b0 = tf32_of(sm[WS + (kb + tq    ) * PW + o]);
                uint32_t b1 = tf32_of(sm[WS + (kb + tq + 4) * PW + o]);
#pragma unroll
                for (int mt = 0; mt < 2; mt++)
                    mma_tf32(acc[mt][nt], a[mt][0], a[mt][1], a[mt][2], a[mt][3], b0, b1);
            }
        }
        __syncthreads();
    }

#pragma unroll
    for (int mt = 0; mt < 2; mt++) {
        int gr = row0 + mwarp + mt * 16 + tg;
#pragma unroll
        for (int nt = 0; nt < 8; nt++) {
            int gc = nwarp + nt * 8 + tq * 2;
            if (gr < N)
                *reinterpret_cast<__half2*>(&g_xlin_h[(size_t)gr * DIM + gc]) =
                    __floats2half2_rn(acc[mt][nt][0], acc[mt][nt][1]);
            if (gr + 8 < N)
                *reinterpret_cast<__half2*>(&g_xlin_h[(size_t)(gr + 8) * DIM + gc]) =
                    __floats2half2_rn(acc[mt][nt][2], acc[mt][nt][3]);
        }
    }
}

// ---------------- gather + accumulate (2 groups x 16 lanes, __ldg) -----------
__device__ __forceinline__ void fma8(float acc[8], uint4 u, float n) {
    const uint32_t* pu = &u.x;
#pragma unroll
    for (int q = 0; q < 4; q++) {
        float2 f = __half22float2(*reinterpret_cast<const __half2*>(&pu[q]));
        acc[q * 2 + 0] += f.x * n;
        acc[q * 2 + 1] += f.y * n;
    }
}

__global__ void k_accum(const float* __restrict__ bias, float* __restrict__ out, int N) {
    int d = blockIdx.x * 8 + (threadIdx.x >> 5);
    int lane = threadIdx.x & 31;
    if (d >= N) return;
    int g = lane >> 4, li = lane & 15;

    float dd = g_dinv[d];
    int start = g_start[d];
    int cnt = g_cnt[d];

    float acc[8];
#pragma unroll
    for (int c = 0; c < 8; c++) acc[c] = 0.f;

    if (g == 0) {
        float s2 = dd * dd;
        uint4 u = __ldg(reinterpret_cast<const uint4*>(g_xlin_h + (size_t)d * DIM + li * 8));
        fma8(acc, u, s2);
    } else {
        float2 b0 = reinterpret_cast<const float2*>(bias)[li * 4 + 0];
        float2 b1 = reinterpret_cast<const float2*>(bias)[li * 4 + 1];
        float2 b2 = reinterpret_cast<const float2*>(bias)[li * 4 + 2];
        float2 b3 = reinterpret_cast<const float2*>(bias)[li * 4 + 3];
        acc[0] += b0.x; acc[1] += b0.y;
        acc[2] += b1.x; acc[3] += b1.y;
        acc[4] += b2.x; acc[5] += b2.y;
        acc[6] += b3.x; acc[7] += b3.y;
    }

    const int2* recs = g_edge + start;
    int k = g;
    for (; k + 2 < cnt; k += 4) {
        int2 r0 = __ldg(&recs[k]);
        int2 r1 = __ldg(&recs[k + 2]);
        uint4 u0 = __ldg(reinterpret_cast<const uint4*>(g_xlin_h + (size_t)r0.x * DIM + li * 8));
        uint4 u1 = __ldg(reinterpret_cast<const uint4*>(g_xlin_h + (size_t)r1.x * DIM + li * 8));
        fma8(acc, u0, __int_as_float(r0.y));
        fma8(acc, u1, __int_as_float(r1.y));
    }
    if (k < cnt) {
        int2 r0 = __ldg(&recs[k]);
        uint4 u0 = __ldg(reinterpret_cast<const uint4*>(g_xlin_h + (size_t)r0.x * DIM + li * 8));
        fma8(acc, u0, __int_as_float(r0.y));
    }

#pragma unroll
    for (int c = 0; c < 8; c++)
        acc[c] += __shfl_xor_sync(0xffffffffu, acc[c], 16);

    if (g == 0) {
        float4* o4 = reinterpret_cast<float4*>(out + (size_t)d * DIM + li * 8);
        o4[0] = make_float4(acc[0], acc[1], acc[2], acc[3]);
        o4[1] = make_float4(acc[4], acc[5], acc[6], acc[7]);
    }
}

// ------------------------------- launcher ------------------------------------
extern "C" void kernel_launch(void* const* d_in, const int* in_sizes, int n_in,
                              void* d_out, int out_size) {
    const float* x  = (const float*)d_in[0];
    const int*   ei = (const int*)d_in[1];
    const float* W  = (const float*)d_in[2];
    const float* b  = (const float*)d_in[3];
    float*       out = (float*)d_out;

    int N = in_sizes[0] / DIM;   // 100000
    int E = in_sizes[1] / 2;     // 1600000

    static cudaStream_t s2 = 0;
    static cudaEvent_t ev_fork = 0, ev_scan = 0, ev_join = 0;
    static void* cnt_addr = 0;
    static bool init_done = false;
    if (!init_done) {
        if (cudaStreamCreateWithFlags(&s2, cudaStreamNonBlocking) != cudaSuccess) s2 = 0;
        cudaEventCreateWithFlags(&ev_fork, cudaEventDisableTiming);
        cudaEventCreateWithFlags(&ev_scan, cudaEventDisableTiming);
        cudaEventCreateWithFlags(&ev_join, cudaEventDisableTiming);
        cudaGetSymbolAddress(&cnt_addr, g_cnt);
        init_done = true;
    }

    const int T = 256;
    int smem_bytes = SM_FLOATS * sizeof(float);
    cudaFuncSetAttribute(k_gemm_mma, cudaFuncAttributeMaxDynamicSharedMemorySize, smem_bytes);

    bool fork = (s2 != 0) && ev_fork && ev_scan && ev_join;
    int Eh = E / 2;

    if (fork) {
        // stream2: GEMM (independent of CSR build)
        cudaEventRecord(ev_fork, 0);
        cudaStreamWaitEvent(s2, ev_fork, 0);
        k_gemm_mma<<<(N + 127) / 128, 256, smem_bytes, s2>>>(x, W, N);

        // stream0: CSR chain through scan3
        cudaMemsetAsync(cnt_addr, 0, (size_t)N * sizeof(int), 0);
        k_hist<<<(E + T - 1) / T, T>>>(ei, E);
        k_scan1<<<SCAN_BLOCKS, SCAN_BS>>>(N);
        k_scan3<<<(N + 255) / 256, 256>>>(N);
        cudaEventRecord(ev_scan, 0);

        // bucket split: half on each stream (s2 half waits for scan3)
        cudaStreamWaitEvent(s2, ev_scan, 0);
        k_bucket<<<(Eh + T - 1) / T, T>>>(ei, E, 0, Eh);
        k_bucket<<<(E - Eh + T - 1) / T, T, 0, s2>>>(ei, E, Eh, E);
        cudaEventRecord(ev_join, s2);
        cudaStreamWaitEvent(0, ev_join, 0);
    } else {
        cudaMemsetAsync(cnt_addr, 0, (size_t)N * sizeof(int), 0);
        k_hist<<<(E + T - 1) / T, T>>>(ei, E);
        k_scan1<<<SCAN_BLOCKS, SCAN_BS>>>(N);
        k_scan3<<<(N + 255) / 256, 256>>>(N);
        k_bucket<<<(E + T - 1) / T, T>>>(ei, E, 0, E);
        k_gemm_mma<<<(N + 127) / 128, 256, smem_bytes>>>(x, W, N);
    }

    k_accum<<<(N + 7) / 8, 256>>>(b, out, N);
}